// round 2
// baseline (speedup 1.0000x reference)
#include <cuda_runtime.h>
#include <cuda_fp16.h>

#define CC 256
#define WW 128
#define HH 64
#define BB 2
#define NCOL (BB*HH)          // 128 independent columns
#define HO 256
#define WO 512
#define NOUT (BB*HO*WO)       // 262144 outputs
#define NSTAT_BLOCKS 512

// scratch (static device arrays; no allocation anywhere)
__device__ float  g_xT[BB*HH*WW*CC];   // [b][h][w][c]  16 MB
__device__ __half g_M[CC*CC];          // packed center-tap weights, row-major [o][c]
__device__ float  g_u[BB*HH*WW];       // reduced (1-channel) pre-upsample result
__device__ float  g_psum[NSTAT_BLOCKS];
__device__ float  g_psumsq[NSTAT_BLOCKS];
__device__ float  g_stats[2];          // mean, inv_std

// ---------------------------------------------------------------------------
// Kernel 0a: extract center tap of conv_w (stride-9 gather) -> packed fp16
__global__ void extract_M_kernel(const float* __restrict__ convw) {
    int i = blockIdx.x * 256 + threadIdx.x;       // i = o*256 + c, i < 65536
    g_M[i] = __float2half(convw[i * 9 + 4]);
}

// ---------------------------------------------------------------------------
// Kernel 0b: transpose p2_r [b][c][h][w] -> g_xT [b][h][w][c]
__global__ void transpose_kernel(const float* __restrict__ p2) {
    __shared__ float tile[32][33];
    int b   = blockIdx.z;
    int hw0 = blockIdx.x * 32;   // over h*w (8192)
    int c0  = blockIdx.y * 32;   // over c (256)
    int tx = threadIdx.x, ty = threadIdx.y;
    const float* in  = p2   + b * CC * HH * WW;
    float*       out = g_xT + b * HH * WW * CC;
#pragma unroll
    for (int k = 0; k < 32; k += 8)
        tile[ty + k][tx] = in[(c0 + ty + k) * (HH * WW) + hw0 + tx];
    __syncthreads();
#pragma unroll
    for (int k = 0; k < 32; k += 8)
        out[(hw0 + ty + k) * CC + c0 + tx] = tile[tx][ty + k];
}

// ---------------------------------------------------------------------------
// Kernel A: the double scan. One CTA per (b,h) column, 256 threads = one
// output channel each. Both scans advance in lockstep so each M element
// loaded from smem feeds 2 FMAs. M is fp16 in smem with XOR-swizzled 16B
// chunks (conflict-free LDS.128); s vectors are broadcast reads.
#define SMEM_BYTES (131072 + 2*2*256*4 + 2*8*4)

__global__ void __launch_bounds__(256, 1) scnn_kernel(const float* __restrict__ w1g) {
    extern __shared__ char smem[];
    uint4* Mh   = (uint4*)smem;                       // 8192 x 16B = 128KB
    float* s1   = (float*)(smem + 131072);            // [2][256]
    float* s2   = s1 + 512;                           // [2][256]
    float* wsum = s2 + 512;                           // [2][8]

    const int tid  = threadIdx.x;
    const int col  = blockIdx.x;                      // b*64 + h
    const int lane = tid & 31;
    const int wid  = tid >> 5;

    // load M: global chunk g -> row o=g>>5, chunk k=g&31, swizzled store
    const uint4* Mg = (const uint4*)g_M;
#pragma unroll
    for (int it = 0; it < 32; it++) {
        int g = it * 256 + tid;
        int o = g >> 5, k = g & 31;
        Mh[(o << 5) | (k ^ (o & 31))] = Mg[g];
    }

    const float w1 = w1g[tid];
    const float* xcol = g_xT + col * (WW * CC);

    // ---- step 0: s1[0] = s2[0] = x[0]; emit u at w'=127
    {
        float xv = xcol[tid];
        s1[tid] = xv;
        s2[tid] = xv;
        float v = w1 * xv;
#pragma unroll
        for (int off = 16; off; off >>= 1) v += __shfl_down_sync(0xffffffffu, v, off);
        if (lane == 0) wsum[wid] = v;                 // buffer 0
    }

    const uint4* Mrow = Mh + (tid << 5);
    const int swz = tid & 31;

    for (int w = 1; w < WW; w++) {
        __syncthreads();
        // thread 0 drains previous step's reduction (overlaps with matvec)
        if (tid == 0) {
            float s = 0.f;
#pragma unroll
            for (int i = 0; i < 8; i++) s += wsum[(((w - 1) & 1) << 3) + i];
            g_u[col * WW + (WW - 1) - (w - 1)] = s;
        }
        const int rd = (w & 1) ^ 1, wr = w & 1;
        const float4* s1r = (const float4*)(s1 + rd * 256);
        const float4* s2r = (const float4*)(s2 + rd * 256);
        float xw = xcol[w * CC + tid];                // global load, hoisted early

        float a1 = 0.f, b1 = 0.f, a2 = 0.f, b2 = 0.f;
#pragma unroll 8
        for (int k = 0; k < 32; k++) {
            uint4 mv = Mrow[k ^ swz];
            float4 p0 = s1r[2 * k], p1 = s1r[2 * k + 1];
            float4 q0 = s2r[2 * k], q1 = s2r[2 * k + 1];
            float2 m0 = __half22float2(*(__half2*)&mv.x);
            float2 m1 = __half22float2(*(__half2*)&mv.y);
            float2 m2 = __half22float2(*(__half2*)&mv.z);
            float2 m3 = __half22float2(*(__half2*)&mv.w);
            a1 = fmaf(m0.x, p0.x, a1);  b1 = fmaf(m0.y, p0.y, b1);
            a1 = fmaf(m1.x, p0.z, a1);  b1 = fmaf(m1.y, p0.w, b1);
            a1 = fmaf(m2.x, p1.x, a1);  b1 = fmaf(m2.y, p1.y, b1);
            a1 = fmaf(m3.x, p1.z, a1);  b1 = fmaf(m3.y, p1.w, b1);
            a2 = fmaf(m0.x, q0.x, a2);  b2 = fmaf(m0.y, q0.y, b2);
            a2 = fmaf(m1.x, q0.z, a2);  b2 = fmaf(m1.y, q0.w, b2);
            a2 = fmaf(m2.x, q1.x, a2);  b2 = fmaf(m2.y, q1.y, b2);
            a2 = fmaf(m3.x, q1.z, a2);  b2 = fmaf(m3.y, q1.w, b2);
        }
        float r1  = fmaxf(a1 + b1, 0.f);
        float r2  = fmaxf(a2 + b2, 0.f);
        float ns1 = xw + r1;                          // s1[w]
        float ns2 = ns1 + r2;                         // s2[w]
        s1[wr * 256 + tid] = ns1;
        s2[wr * 256 + tid] = ns2;

        float v = w1 * ns2;
#pragma unroll
        for (int off = 16; off; off >>= 1) v += __shfl_down_sync(0xffffffffu, v, off);
        if (lane == 0) wsum[(wr << 3) + wid] = v;
    }
    __syncthreads();
    if (tid == 0) {
        float s = 0.f;
#pragma unroll
        for (int i = 0; i < 8; i++) s += wsum[8 + i];  // last step wrote buffer 1
        g_u[col * WW + 0] = s;
    }
}

// ---------------------------------------------------------------------------
// bilinear upsample (align-corners semantics matching the reference)
__device__ __forceinline__ float upsample_val(int idx) {
    int j = idx & (WO - 1);
    int r = idx >> 9;
    int i = r & (HO - 1);
    int b = r >> 8;
    float ys  = (float)i * (float)(63.0 / 255.0);
    float y0f = floorf(ys);
    int   y0  = (int)y0f;
    float wy  = ys - y0f;
    int   y1  = min(y0 + 1, HH - 1);
    float xs  = (float)j * (float)(127.0 / 511.0);
    float x0f = floorf(xs);
    int   x0  = (int)x0f;
    float wx  = xs - x0f;
    int   x1  = min(x0 + 1, WW - 1);
    const float* ub = g_u + b * (HH * WW);
    float u00 = ub[y0 * WW + x0], u01 = ub[y0 * WW + x1];
    float u10 = ub[y1 * WW + x0], u11 = ub[y1 * WW + x1];
    float r0 = u00 * (1.f - wy) + u10 * wy;
    float r1 = u01 * (1.f - wy) + u11 * wy;
    return r0 * (1.f - wx) + r1 * wx;
}

// Kernel B1: per-block partial sums of upsampled values (deterministic)
__global__ void stats_kernel() {
    __shared__ float ss[256], sq[256];
    int t = threadIdx.x;
    float sum = 0.f, sumsq = 0.f;
#pragma unroll
    for (int rr = 0; rr < 2; rr++) {
        int idx = blockIdx.x * 512 + rr * 256 + t;
        float v = upsample_val(idx);
        sum += v;
        sumsq += v * v;
    }
    ss[t] = sum; sq[t] = sumsq;
    __syncthreads();
    for (int s = 128; s; s >>= 1) {
        if (t < s) { ss[t] += ss[t + s]; sq[t] += sq[t + s]; }
        __syncthreads();
    }
    if (t == 0) { g_psum[blockIdx.x] = ss[0]; g_psumsq[blockIdx.x] = sq[0]; }
}

// Kernel B2: final reduction -> mean, inv_std
__global__ void finalize_stats_kernel() {
    __shared__ float ss[NSTAT_BLOCKS], sq[NSTAT_BLOCKS];
    int t = threadIdx.x;
    ss[t] = g_psum[t]; sq[t] = g_psumsq[t];
    __syncthreads();
    for (int s = NSTAT_BLOCKS / 2; s; s >>= 1) {
        if (t < s) { ss[t] += ss[t + s]; sq[t] += sq[t + s]; }
        __syncthreads();
    }
    if (t == 0) {
        float inv_n = 1.0f / (float)NOUT;
        float mean  = ss[0] * inv_n;
        float var   = sq[0] * inv_n - mean * mean;
        g_stats[0] = mean;
        g_stats[1] = rsqrtf(var + 1e-5f);
    }
}

// Kernel B3: recompute upsample, apply BN + sigmoid
__global__ void output_kernel(float* __restrict__ out,
                              const float* __restrict__ gamma,
                              const float* __restrict__ beta) {
    int idx = blockIdx.x * 256 + threadIdx.x;
    float v = upsample_val(idx);
    float y = (v - g_stats[0]) * g_stats[1] * gamma[0] + beta[0];
    out[idx] = 1.0f / (1.0f + expf(-y));
}

// ---------------------------------------------------------------------------
extern "C" void kernel_launch(void* const* d_in, const int* in_sizes, int n_in,
                              void* d_out, int out_size) {
    const float* p2    = (const float*)d_in[0];   // (2,256,64,128)
    const float* convw = (const float*)d_in[1];   // (256,256,1,9)
    const float* conv1 = (const float*)d_in[2];   // (1,256,1,1)
    const float* gamma = (const float*)d_in[3];
    const float* beta  = (const float*)d_in[4];
    float* out = (float*)d_out;

    cudaFuncSetAttribute(scnn_kernel, cudaFuncAttributeMaxDynamicSharedMemorySize,
                         SMEM_BYTES);

    extract_M_kernel<<<256, 256>>>(convw);
    transpose_kernel<<<dim3(256, 8, 2), dim3(32, 8)>>>(p2);
    scnn_kernel<<<NCOL, 256, SMEM_BYTES>>>(conv1);
    stats_kernel<<<NSTAT_BLOCKS, 256>>>();
    finalize_stats_kernel<<<1, NSTAT_BLOCKS>>>();
    output_kernel<<<NOUT / 256, 256>>>(out, gamma, beta);
}

// round 4
// speedup vs baseline: 2.6874x; 2.6874x over previous
#include <cuda_runtime.h>
#include <cuda_fp16.h>
#include <cstdint>

#define CC 256
#define WW 128
#define HH 64
#define BB 2
#define NCOL (BB*HH)          // 128 independent columns
#define HO 256
#define WO 512
#define NOUT (BB*HO*WO)       // 262144 outputs
#define NSTAT_BLOCKS 512

// scratch (static device arrays; no allocation anywhere)
__device__ float  g_xT[BB*HH*WW*CC];    // [col][w][c]  16 MB
__device__ __half g_M[CC*CC];           // center-tap weights fp16, row-major [o][c]
__device__ float  g_u[NCOL*WW];         // reduced (1-channel) pre-upsample result
__device__ float  g_psum[NSTAT_BLOCKS];
__device__ float  g_psumsq[NSTAT_BLOCKS];
__device__ float  g_stats[2];           // mean, inv_std

// ===========================================================================
// Kernel 0a: extract center tap of conv_w -> packed fp16
__global__ void extract_M_kernel(const float* __restrict__ convw) {
    int i = blockIdx.x * 256 + threadIdx.x;       // i = o*256 + c
    g_M[i] = __float2half(convw[i * 9 + 4]);
}

// Kernel 0b: transpose p2_r [b][c][h][w] -> g_xT [b][h][w][c]
__global__ void transpose_kernel(const float* __restrict__ p2) {
    __shared__ float tile[32][33];
    int b   = blockIdx.z;
    int hw0 = blockIdx.x * 32;
    int c0  = blockIdx.y * 32;
    int tx = threadIdx.x, ty = threadIdx.y;
    const float* in  = p2   + b * CC * HH * WW;
    float*       out = g_xT + b * HH * WW * CC;
#pragma unroll
    for (int k = 0; k < 32; k += 8)
        tile[ty + k][tx] = in[(c0 + ty + k) * (HH * WW) + hw0 + tx];
    __syncthreads();
#pragma unroll
    for (int k = 0; k < 32; k += 8)
        out[(hw0 + ty + k) * CC + c0 + tx] = tile[tx][ty + k];
}

// ===========================================================================
// Kernel A: HMMA-driven double scan. 32 CTAs x 4 columns, 256 threads.
// Per step w: D[256x8] = M[256x256] @ S[256x8] via mma.sync m16n8k16
// (A = M resident in registers; B = S fp16 in double-buffered smem).
// B logical layout: B[n][k], n = 2*col_in_group + scan (scan0=s1, scan1=s2),
// k = channel. Row stride 528 bytes -> conflict-free LDS.32 B-fragment loads.
// Epilogue (all in registers): s1' = x + relu(d_s1); s2' = s1' + relu(d_s2);
// dot(w1, s2') folded in via shfl reduction.
#define BSTRIDE 528

__global__ void __launch_bounds__(256, 1) scnn_hmma_kernel(const float* __restrict__ w1g) {
    __shared__ __align__(16) unsigned char Bbuf[2][8 * BSTRIDE];
    __shared__ float wsum[2][8][4];

    const int tid  = threadIdx.x;
    const int wid  = tid >> 5;
    const int lane = tid & 31;
    const int tg   = lane & 3;     // thread-in-group: selects column of group
    const int g    = lane >> 2;    // group id: row within 8
    const int col0 = blockIdx.x * 4;
    const int col  = col0 + tg;

    // ---- A fragments: M rows [32*wid, 32*wid+32), resident in registers.
    // m16n8k16 A frag: a0=(g,2tg..), a1=(g+8,2tg..), a2=(g,2tg+8..), a3=(g+8,2tg+8..)
    uint32_t A[2][16][4];
#pragma unroll
    for (int tt = 0; tt < 2; tt++) {
        int rlo = 32 * wid + 16 * tt + g;
        const uint32_t* Mlo = reinterpret_cast<const uint32_t*>(g_M + rlo * CC);
        const uint32_t* Mhi = reinterpret_cast<const uint32_t*>(g_M + (rlo + 8) * CC);
#pragma unroll
        for (int kt = 0; kt < 16; kt++) {
            A[tt][kt][0] = Mlo[kt * 8 + tg];
            A[tt][kt][1] = Mhi[kt * 8 + tg];
            A[tt][kt][2] = Mlo[kt * 8 + tg + 4];
            A[tt][kt][3] = Mhi[kt * 8 + tg + 4];
        }
    }

    // this thread's 4 channel rows (D-fragment rows) and w1 taps
    int   ch[4];
    float w1v[4];
#pragma unroll
    for (int i = 0; i < 4; i++) {
        int tt = i >> 1, h = i & 1;
        ch[i]  = 32 * wid + 16 * tt + 8 * h + g;
        w1v[i] = w1g[ch[i]];
    }

    const float* xcol = g_xT + col * (WW * CC);

    // ---- step 0: s1[0] = s2[0] = x[:,0]
    float xv[4];
    {
        float usum = 0.f;
#pragma unroll
        for (int i = 0; i < 4; i++) {
            float x0 = xcol[ch[i]];
            unsigned short hx = __half_as_ushort(__float2half_rn(x0));
            *(unsigned short*)(&Bbuf[0][(2 * tg)     * BSTRIDE + ch[i] * 2]) = hx;
            *(unsigned short*)(&Bbuf[0][(2 * tg + 1) * BSTRIDE + ch[i] * 2]) = hx;
            usum += w1v[i] * x0;
            xv[i] = xcol[CC + ch[i]];          // prefetch x[:,1]
        }
        usum += __shfl_xor_sync(0xffffffffu, usum, 4);
        usum += __shfl_xor_sync(0xffffffffu, usum, 8);
        usum += __shfl_xor_sync(0xffffffffu, usum, 16);
        if (lane < 4) wsum[0][wid][lane] = usum;
    }

    for (int w = 1; w < WW; w++) {
        __syncthreads();
        // drain previous step's u reduction
        if (tid < 4) {
            float s = 0.f;
#pragma unroll
            for (int q = 0; q < 8; q++) s += wsum[(w - 1) & 1][q][tid];
            g_u[(col0 + tid) * WW + (WW - 1) - (w - 1)] = s;
        }

        const unsigned char* Bp = Bbuf[(w - 1) & 1];
        float d[2][4] = {{0.f, 0.f, 0.f, 0.f}, {0.f, 0.f, 0.f, 0.f}};
#pragma unroll
        for (int kt = 0; kt < 16; kt++) {
            uint32_t b0 = *(const uint32_t*)(Bp + g * BSTRIDE + kt * 32 + tg * 4);
            uint32_t b1 = *(const uint32_t*)(Bp + g * BSTRIDE + kt * 32 + tg * 4 + 16);
#pragma unroll
            for (int tt = 0; tt < 2; tt++) {
                asm volatile(
                    "mma.sync.aligned.m16n8k16.row.col.f32.f16.f16.f32 "
                    "{%0,%1,%2,%3}, {%4,%5,%6,%7}, {%8,%9}, {%0,%1,%2,%3};"
                    : "+f"(d[tt][0]), "+f"(d[tt][1]), "+f"(d[tt][2]), "+f"(d[tt][3])
                    : "r"(A[tt][kt][0]), "r"(A[tt][kt][1]),
                      "r"(A[tt][kt][2]), "r"(A[tt][kt][3]),
                      "r"(b0), "r"(b1));
            }
        }

        // prefetch next x while nothing depends on it yet
        float xn[4] = {0.f, 0.f, 0.f, 0.f};
        if (w < WW - 1) {
#pragma unroll
            for (int i = 0; i < 4; i++) xn[i] = xcol[(w + 1) * CC + ch[i]];
        }

        unsigned char* Bn = Bbuf[w & 1];
        float usum = 0.f;
#pragma unroll
        for (int i = 0; i < 4; i++) {
            int tt = i >> 1, h = i & 1;
            float s1n = xv[i] + fmaxf(d[tt][2 * h],     0.f);
            float s2n = s1n   + fmaxf(d[tt][2 * h + 1], 0.f);
            usum += w1v[i] * s2n;
            if (w < WW - 1) {
                *(unsigned short*)(Bn + (2 * tg)     * BSTRIDE + ch[i] * 2) =
                    __half_as_ushort(__float2half_rn(s1n));
                *(unsigned short*)(Bn + (2 * tg + 1) * BSTRIDE + ch[i] * 2) =
                    __half_as_ushort(__float2half_rn(s2n));
                xv[i] = xn[i];
            }
        }
        usum += __shfl_xor_sync(0xffffffffu, usum, 4);
        usum += __shfl_xor_sync(0xffffffffu, usum, 8);
        usum += __shfl_xor_sync(0xffffffffu, usum, 16);
        if (lane < 4) wsum[w & 1][wid][lane] = usum;
    }

    __syncthreads();
    if (tid < 4) {
        float s = 0.f;
#pragma unroll
        for (int q = 0; q < 8; q++) s += wsum[1][q][tid];
        g_u[(col0 + tid) * WW + 0] = s;
    }
}

// ===========================================================================
// bilinear upsample (align-corners semantics matching the reference)
__device__ __forceinline__ float upsample_val(int idx) {
    int j = idx & (WO - 1);
    int rr = idx >> 9;
    int i = rr & (HO - 1);
    int b = rr >> 8;
    float ys  = (float)i * (float)(63.0 / 255.0);
    float y0f = floorf(ys);
    int   y0  = (int)y0f;
    float wy  = ys - y0f;
    int   y1  = min(y0 + 1, HH - 1);
    float xs  = (float)j * (float)(127.0 / 511.0);
    float x0f = floorf(xs);
    int   x0  = (int)x0f;
    float wx  = xs - x0f;
    int   x1  = min(x0 + 1, WW - 1);
    const float* ub = g_u + b * (HH * WW);
    float u00 = ub[y0 * WW + x0], u01 = ub[y0 * WW + x1];
    float u10 = ub[y1 * WW + x0], u11 = ub[y1 * WW + x1];
    float r0 = u00 * (1.f - wy) + u10 * wy;
    float r1 = u01 * (1.f - wy) + u11 * wy;
    return r0 * (1.f - wx) + r1 * wx;
}

__global__ void stats_kernel() {
    __shared__ float ss[256], sq[256];
    int t = threadIdx.x;
    float sum = 0.f, sumsq = 0.f;
#pragma unroll
    for (int rr = 0; rr < 2; rr++) {
        int idx = blockIdx.x * 512 + rr * 256 + t;
        float v = upsample_val(idx);
        sum += v;
        sumsq += v * v;
    }
    ss[t] = sum; sq[t] = sumsq;
    __syncthreads();
    for (int s = 128; s; s >>= 1) {
        if (t < s) { ss[t] += ss[t + s]; sq[t] += sq[t + s]; }
        __syncthreads();
    }
    if (t == 0) { g_psum[blockIdx.x] = ss[0]; g_psumsq[blockIdx.x] = sq[0]; }
}

__global__ void finalize_stats_kernel() {
    __shared__ float ss[NSTAT_BLOCKS], sq[NSTAT_BLOCKS];
    int t = threadIdx.x;
    ss[t] = g_psum[t]; sq[t] = g_psumsq[t];
    __syncthreads();
    for (int s = NSTAT_BLOCKS / 2; s; s >>= 1) {
        if (t < s) { ss[t] += ss[t + s]; sq[t] += sq[t + s]; }
        __syncthreads();
    }
    if (t == 0) {
        float inv_n = 1.0f / (float)NOUT;
        float mean  = ss[0] * inv_n;
        float var   = sq[0] * inv_n - mean * mean;
        g_stats[0] = mean;
        g_stats[1] = rsqrtf(var + 1e-5f);
    }
}

__global__ void output_kernel(float* __restrict__ out,
                              const float* __restrict__ gamma,
                              const float* __restrict__ beta) {
    int idx = blockIdx.x * 256 + threadIdx.x;
    float v = upsample_val(idx);
    float y = (v - g_stats[0]) * g_stats[1] * gamma[0] + beta[0];
    out[idx] = 1.0f / (1.0f + expf(-y));
}

// ===========================================================================
extern "C" void kernel_launch(void* const* d_in, const int* in_sizes, int n_in,
                              void* d_out, int out_size) {
    const float* p2    = (const float*)d_in[0];   // (2,256,64,128)
    const float* convw = (const float*)d_in[1];   // (256,256,1,9)
    const float* conv1 = (const float*)d_in[2];   // (1,256,1,1)
    const float* gamma = (const float*)d_in[3];
    const float* beta  = (const float*)d_in[4];
    float* out = (float*)d_out;

    extract_M_kernel<<<256, 256>>>(convw);
    transpose_kernel<<<dim3(256, 8, 2), dim3(32, 8)>>>(p2);
    scnn_hmma_kernel<<<32, 256>>>(conv1);
    stats_kernel<<<NSTAT_BLOCKS, 256>>>();
    finalize_stats_kernel<<<1, NSTAT_BLOCKS>>>();
    output_kernel<<<NOUT / 256, 256>>>(out, gamma, beta);
}

// round 5
// speedup vs baseline: 2.7608x; 1.0273x over previous
#include <cuda_runtime.h>
#include <cuda_fp16.h>
#include <cstdint>

#define CC 256
#define WW 128
#define HH 64
#define BB 2
#define NCOL (BB*HH)          // 128 independent columns
#define HO 256
#define WO 512
#define NOUT (BB*HO*WO)       // 262144 outputs
#define NROWS 512             // output rows (b,i)

// scratch (static device arrays; no allocation anywhere)
__device__ __half g_M[CC*CC];           // center-tap weights fp16, row-major [o][c]
__device__ float  g_u[NCOL*WW];         // reduced (1-channel) pre-upsample result
__device__ float  g_psum[NROWS];
__device__ float  g_psumsq[NROWS];
__device__ float  g_stats[2];           // mean, inv_std

__device__ __forceinline__ uint32_t smem_u32(const void* p) {
    uint32_t a;
    asm("{ .reg .u64 t; cvta.to.shared.u64 t, %1; cvt.u32.u64 %0, t; }"
        : "=r"(a) : "l"(p));
    return a;
}

// ===========================================================================
// Kernel 0: extract center tap of conv_w -> packed fp16
__global__ void extract_M_kernel(const float* __restrict__ convw) {
    int i = blockIdx.x * 256 + threadIdx.x;       // i = o*256 + c
    g_M[i] = __float2half(convw[i * 9 + 4]);
}

// ===========================================================================
// Kernel A: HMMA-driven double scan. 32 CTAs x 4 columns, 256 threads.
// Per step w: D[256x8] = M[256x256] @ S[256x8] via mma.sync m16n8k16.
// A = M resident in registers. B = S fp16 in double-buffered smem, k-major
// layout B[k][n] (16B per k-row) -> ldmatrix.x4.trans B-fragment loads and
// packed half2 epilogue stores, both conflict-free.
// x is loaded straight from p2_r (native layout: contiguous in w) as one
// float4 per thread per 4 steps, prefetched ~3 steps ahead.
#define MMA_ASM(dd, a, b0r, b1r)                                              \
    asm volatile(                                                             \
        "mma.sync.aligned.m16n8k16.row.col.f32.f16.f16.f32 "                  \
        "{%0,%1,%2,%3}, {%4,%5,%6,%7}, {%8,%9}, {%0,%1,%2,%3};"               \
        : "+f"((dd)[0]), "+f"((dd)[1]), "+f"((dd)[2]), "+f"((dd)[3])          \
        : "r"((a)[0]), "r"((a)[1]), "r"((a)[2]), "r"((a)[3]),                 \
          "r"(b0r), "r"(b1r))

__global__ void __launch_bounds__(256, 1) scnn_hmma_kernel(
        const float* __restrict__ p2, const float* __restrict__ w1g) {
    __shared__ __align__(128) __half Bbuf[2][CC * 8];   // [buf][k*8 + n] 8KB
    __shared__ float wsum[2][8][4];

    const int tid  = threadIdx.x;
    const int wid  = tid >> 5;
    const int lane = tid & 31;
    const int tg   = lane & 3;     // selects column of group (and n pair)
    const int g    = lane >> 2;
    const int col0 = blockIdx.x * 4;
    const int col  = col0 + tg;
    const int b    = col >> 6;
    const int h    = col & 63;

    // ---- A fragments: M rows [32*wid, 32*wid+32), resident in registers
    uint32_t A[2][16][4];
#pragma unroll
    for (int tt = 0; tt < 2; tt++) {
        int rlo = 32 * wid + 16 * tt + g;
        const uint32_t* Mlo = reinterpret_cast<const uint32_t*>(g_M + rlo * CC);
        const uint32_t* Mhi = reinterpret_cast<const uint32_t*>(g_M + (rlo + 8) * CC);
#pragma unroll
        for (int kt = 0; kt < 16; kt++) {
            A[tt][kt][0] = Mlo[kt * 8 + tg];
            A[tt][kt][1] = Mhi[kt * 8 + tg];
            A[tt][kt][2] = Mlo[kt * 8 + tg + 4];
            A[tt][kt][3] = Mhi[kt * 8 + tg + 4];
        }
    }

    // this thread's 4 channel rows and w1 taps
    int   ch[4];
    float w1v[4];
#pragma unroll
    for (int i = 0; i < 4; i++) {
        int tt = i >> 1, hh = i & 1;
        ch[i]  = 32 * wid + 16 * tt + 8 * hh + g;
        w1v[i] = w1g[ch[i]];
    }

    // x stream pointers: contiguous in w for fixed (b, ch, h)
    const float4* xp[4];
#pragma unroll
    for (int i = 0; i < 4; i++)
        xp[i] = reinterpret_cast<const float4*>(
            p2 + ((size_t)(b * CC + ch[i]) * HH + h) * WW);

    float4 cur[4], nxt[4];
#pragma unroll
    for (int i = 0; i < 4; i++) cur[i] = xp[i][0];

    const uint32_t b32    = smem_u32(&Bbuf[0][0]);
    const uint32_t lmaddr = b32 + (uint32_t)lane * 16u;

    // ---- step 0: s1[0] = s2[0] = x[:,0]  (write buffer 0)
    {
        float usum = 0.f;
#pragma unroll
        for (int i = 0; i < 4; i++) {
            float x0 = cur[i].x;
            __half hx = __float2half_rn(x0);
            *(__half2*)&Bbuf[0][ch[i] * 8 + 2 * tg] = __halves2half2(hx, hx);
            usum += w1v[i] * x0;
        }
        usum += __shfl_xor_sync(0xffffffffu, usum, 4);
        usum += __shfl_xor_sync(0xffffffffu, usum, 8);
        usum += __shfl_xor_sync(0xffffffffu, usum, 16);
        if (lane < 4) wsum[0][wid][lane] = usum;
    }

    for (int q = 0; q < 32; q++) {
#pragma unroll
        for (int j = 0; j < 4; j++) {
            const int w = 4 * q + 1 + j;
            if (w > 127) break;
            __syncthreads();
            // drain previous step's u reduction
            if (tid < 4) {
                float s = 0.f;
#pragma unroll
                for (int k8 = 0; k8 < 8; k8++) s += wsum[(w - 1) & 1][k8][tid];
                g_u[(col0 + tid) * WW + (WW - w)] = s;
            }

            const int rb = j & 1;           // read buffer = (w-1)&1
            const int wb = rb ^ 1;          // write buffer = w&1
            const uint32_t base = lmaddr + (uint32_t)rb * (CC * 8 * 2);

            uint32_t L[8][4];
#pragma unroll
            for (int m8 = 0; m8 < 8; m8++) {
                asm volatile(
                    "ldmatrix.sync.aligned.m8n8.x4.trans.shared.b16 "
                    "{%0,%1,%2,%3}, [%4];"
                    : "=r"(L[m8][0]), "=r"(L[m8][1]),
                      "=r"(L[m8][2]), "=r"(L[m8][3])
                    : "r"(base + (uint32_t)m8 * 512u));
            }

            // prefetch next x group while MMAs run
            if (j == 0 && q < 31) {
#pragma unroll
                for (int i = 0; i < 4; i++) nxt[i] = xp[i][q + 1];
            }

            float d[2][4] = {{0.f,0.f,0.f,0.f},{0.f,0.f,0.f,0.f}};
            float e[2][4] = {{0.f,0.f,0.f,0.f},{0.f,0.f,0.f,0.f}};
#pragma unroll
            for (int m8 = 0; m8 < 8; m8++) {
#pragma unroll
                for (int tt = 0; tt < 2; tt++) {
                    MMA_ASM(d[tt], A[tt][2 * m8],     L[m8][0], L[m8][1]);
                    MMA_ASM(e[tt], A[tt][2 * m8 + 1], L[m8][2], L[m8][3]);
                }
            }

            float usum = 0.f;
#pragma unroll
            for (int i = 0; i < 4; i++) {
                const int tt = i >> 1, hh = i & 1;
                float xvj = (j == 0) ? cur[i].y
                          : (j == 1) ? cur[i].z
                          : (j == 2) ? cur[i].w
                                     : nxt[i].x;
                float r1  = fmaxf(d[tt][2*hh]   + e[tt][2*hh],   0.f);
                float r2  = fmaxf(d[tt][2*hh+1] + e[tt][2*hh+1], 0.f);
                float s1n = xvj + r1;
                float s2n = s1n + r2;
                usum += w1v[i] * s2n;
                if (w < 127)
                    *(__half2*)&Bbuf[wb][ch[i] * 8 + 2 * tg] =
                        __halves2half2(__float2half_rn(s1n), __float2half_rn(s2n));
            }
            usum += __shfl_xor_sync(0xffffffffu, usum, 4);
            usum += __shfl_xor_sync(0xffffffffu, usum, 8);
            usum += __shfl_xor_sync(0xffffffffu, usum, 16);
            if (lane < 4) wsum[w & 1][wid][lane] = usum;

            if (j == 3) {
                cur[0] = nxt[0]; cur[1] = nxt[1];
                cur[2] = nxt[2]; cur[3] = nxt[3];
            }
        }
    }

    __syncthreads();
    if (tid < 4) {
        float s = 0.f;
#pragma unroll
        for (int k8 = 0; k8 < 8; k8++) s += wsum[1][k8][tid];   // w=127 -> buf 1
        g_u[(col0 + tid) * WW + 0] = s;
    }
}

// ===========================================================================
// Upsample helpers: one block per output row (b,i); stage the two needed
// u-rows (y0,y1) in smem, compute 512 bilinear values from LDS.
__device__ __forceinline__ void stage_rows(float* su0, float* su1,
                                           int b, int i, float& wy) {
    float ys = (float)i * (63.0f / 255.0f);
    int y0 = (int)ys;
    wy = ys - (float)y0;
    int y1 = min(y0 + 1, HH - 1);
    int t = threadIdx.x;
    if (t < 128)      su0[t]       = g_u[(b * HH + y0) * WW + t];
    else              su1[t - 128] = g_u[(b * HH + y1) * WW + (t - 128)];
    __syncthreads();
}

__device__ __forceinline__ float bilin(const float* su0, const float* su1,
                                       int j, float wy) {
    float xs = (float)j * (127.0f / 511.0f);
    int x0 = (int)xs;
    float wx = xs - (float)x0;
    int x1 = min(x0 + 1, WW - 1);
    float r0 = su0[x0] * (1.f - wy) + su1[x0] * wy;
    float r1 = su0[x1] * (1.f - wy) + su1[x1] * wy;
    return r0 * (1.f - wx) + r1 * wx;
}

__global__ void stats_kernel() {
    __shared__ float su0[128], su1[128];
    __shared__ float rs[8], rq[8];
    int row = blockIdx.x;                 // b*256 + i
    int b = row >> 8, i = row & 255;
    float wy;
    stage_rows(su0, su1, b, i, wy);

    int t = threadIdx.x;
    float sum = 0.f, sq = 0.f;
#pragma unroll
    for (int rr = 0; rr < 2; rr++) {
        float v = bilin(su0, su1, t + rr * 256, wy);
        sum += v;
        sq  += v * v;
    }
#pragma unroll
    for (int o = 16; o; o >>= 1) {
        sum += __shfl_xor_sync(0xffffffffu, sum, o);
        sq  += __shfl_xor_sync(0xffffffffu, sq,  o);
    }
    if ((t & 31) == 0) { rs[t >> 5] = sum; rq[t >> 5] = sq; }
    __syncthreads();
    if (t == 0) {
        float a = 0.f, c = 0.f;
#pragma unroll
        for (int k = 0; k < 8; k++) { a += rs[k]; c += rq[k]; }
        g_psum[row] = a; g_psumsq[row] = c;
    }
}

__global__ void finalize_stats_kernel() {
    __shared__ float ss[NROWS], sq[NROWS];
    int t = threadIdx.x;
    ss[t] = g_psum[t]; sq[t] = g_psumsq[t];
    __syncthreads();
    for (int s = NROWS / 2; s; s >>= 1) {
        if (t < s) { ss[t] += ss[t + s]; sq[t] += sq[t + s]; }
        __syncthreads();
    }
    if (t == 0) {
        float inv_n = 1.0f / (float)NOUT;
        float mean  = ss[0] * inv_n;
        float var   = sq[0] * inv_n - mean * mean;
        g_stats[0] = mean;
        g_stats[1] = rsqrtf(var + 1e-5f);
    }
}

__global__ void output_kernel(float* __restrict__ out,
                              const float* __restrict__ gamma,
                              const float* __restrict__ beta) {
    __shared__ float su0[128], su1[128];
    int row = blockIdx.x;
    int b = row >> 8, i = row & 255;
    float wy;
    stage_rows(su0, su1, b, i, wy);

    float mean = g_stats[0], istd = g_stats[1];
    float gm = gamma[0], bt = beta[0];
    int t = threadIdx.x;
#pragma unroll
    for (int rr = 0; rr < 2; rr++) {
        int j = t + rr * 256;
        float v = bilin(su0, su1, j, wy);
        float y = (v - mean) * istd * gm + bt;
        out[row * WO + j] = 1.0f / (1.0f + expf(-y));
    }
}

// ===========================================================================
extern "C" void kernel_launch(void* const* d_in, const int* in_sizes, int n_in,
                              void* d_out, int out_size) {
    const float* p2    = (const float*)d_in[0];   // (2,256,64,128)
    const float* convw = (const float*)d_in[1];   // (256,256,1,9)
    const float* conv1 = (const float*)d_in[2];   // (1,256,1,1)
    const float* gamma = (const float*)d_in[3];
    const float* beta  = (const float*)d_in[4];
    float* out = (float*)d_out;

    extract_M_kernel<<<256, 256>>>(convw);
    scnn_hmma_kernel<<<32, 256>>>(p2, conv1);
    stats_kernel<<<NROWS, 256>>>();
    finalize_stats_kernel<<<1, NROWS>>>();
    output_kernel<<<NROWS, 256>>>(out, gamma, beta);
}